// round 11
// baseline (speedup 1.0000x reference)
#include <cuda_runtime.h>
#include <cuda_bf16.h>
#include <cstdint>

#define B_   16
#define C_   256
#define HW_  4096          // 64*64
#define NTOT (B_ * C_ * HW_)

// ---------------- scratch + folded weights (device globals: no allocs) -----
__device__ float g_bufA[NTOT];
__device__ float g_bufB[NTOT];

__device__ __nv_bfloat16 g_w1_hi[C_ * C_], g_w1_lo[C_ * C_];
__device__ __nv_bfloat16 g_w2_hi[C_ * C_], g_w2_lo[C_ * C_];
__device__ __nv_bfloat16 g_w3_hi[C_ * C_], g_w3_lo[C_ * C_];
__device__ float g_b1[C_], g_b2[C_], g_b3[C_];
__device__ float g_wd[C_ * 81];   // combined 9x9 depthwise (incl. identity)
__device__ float g_bd[C_];        // combined depthwise bias

// ---------------- weight folding (BN -> 1x1 weights, 4 dw -> one 9x9) ------
__global__ void fold_kernel(
    const float* __restrict__ pre_w,
    const float* __restrict__ bn1_g, const float* __restrict__ bn1_b,
    const float* __restrict__ bn1_m, const float* __restrict__ bn1_v,
    const float* __restrict__ dw3_w, const float* __restrict__ dw3_b,
    const float* __restrict__ dw5_w, const float* __restrict__ dw5_b,
    const float* __restrict__ dw7_w, const float* __restrict__ dw7_b,
    const float* __restrict__ dw9_w, const float* __restrict__ dw9_b,
    const float* __restrict__ pw_w,
    const float* __restrict__ bn2_g, const float* __restrict__ bn2_b,
    const float* __restrict__ bn2_m, const float* __restrict__ bn2_v,
    const float* __restrict__ post_w,
    const float* __restrict__ bn3_g, const float* __restrict__ bn3_b,
    const float* __restrict__ bn3_m, const float* __restrict__ bn3_v)
{
    int oc = blockIdx.x;
    int ic = threadIdx.x;
    float s1 = bn1_g[oc] * rsqrtf(bn1_v[oc] + 1e-5f);
    float s2 = bn2_g[oc] * rsqrtf(bn2_v[oc] + 1e-5f);
    float s3 = bn3_g[oc] * rsqrtf(bn3_v[oc] + 1e-5f);
    int idx = oc * C_ + ic;

    float w1 = pre_w[idx] * s1;
    __nv_bfloat16 h1 = __float2bfloat16(w1);
    g_w1_hi[idx] = h1;
    g_w1_lo[idx] = __float2bfloat16(w1 - __bfloat162float(h1));

    float w2 = pw_w[idx] * s2;
    __nv_bfloat16 h2 = __float2bfloat16(w2);
    g_w2_hi[idx] = h2;
    g_w2_lo[idx] = __float2bfloat16(w2 - __bfloat162float(h2));

    float w3 = post_w[idx] * s3;
    __nv_bfloat16 h3 = __float2bfloat16(w3);
    g_w3_hi[idx] = h3;
    g_w3_lo[idx] = __float2bfloat16(w3 - __bfloat162float(h3));

    if (ic == 0) {
        g_b1[oc] = bn1_b[oc] - bn1_m[oc] * s1;
        g_b2[oc] = bn2_b[oc] - bn2_m[oc] * s2;
        g_b3[oc] = bn3_b[oc] - bn3_m[oc] * s3;
    }
    // combined depthwise 9x9 (cross-correlation, no flip; all same-padded)
    if (ic < 81) {
        int r = ic / 9, s = ic - 9 * r;
        float v = dw9_w[oc * 81 + ic];
        if (r >= 1 && r <= 7 && s >= 1 && s <= 7) v += dw7_w[oc * 49 + (r - 1) * 7 + (s - 1)];
        if (r >= 2 && r <= 6 && s >= 2 && s <= 6) v += dw5_w[oc * 25 + (r - 2) * 5 + (s - 2)];
        if (r >= 3 && r <= 5 && s >= 3 && s <= 5) v += dw3_w[oc * 9  + (r - 3) * 3 + (s - 3)];
        if (ic == 40) v += 1.0f;   // identity branch (center tap)
        g_wd[oc * 81 + ic] = v;
    }
    if (ic == 81) g_bd[oc] = dw3_b[oc] + dw5_b[oc] + dw7_b[oc] + dw9_b[oc];
}

// ---------------- bf16-split GEMM v5: 64x128 tile, 3 CTAs/SM ---------------
// (tcgen05 is unavailable: harness lowers via compute_103, no 'a' features.)
// C[oc][n] = relu( sum_ic W[oc][ic] * X[ic][n] + bias[oc] )
// Split: acc += Whi*Xhi + Whi*Xlo + Wlo*Xhi  (~fp32 accuracy)
// W in smem [m][k] pitch 40 bf16 (80B rows, conflict-free LDSM phases).
// X in smem [k][n] pitch 136 bf16 (272B rows), B frags via ldmatrix.trans.
// 64 M-rows per CTA -> 32 accum regs/thread -> 3 CTAs/SM (84-reg cap).
// grid = (4, 512): the four tile_m CTAs sharing X columns are bid-adjacent.

#define WPITCH 40
#define XPITCH 136
#define SW_BYTES (64 * WPITCH * 2)         // 5120 per stage (one of hi/lo)
#define SX_BYTES (32 * XPITCH * 2)         // 8704 per stage
#define OFF_WHI 0
#define OFF_WLO (2 * SW_BYTES)             // 10240
#define OFF_XHI (4 * SW_BYTES)             // 20480
#define OFF_XLO (OFF_XHI + 2 * SX_BYTES)   // 37888
#define SMEM_TOT (OFF_XLO + 2 * SX_BYTES)  // 55296

__device__ __forceinline__ void mma_bf16(float* c, const unsigned* a, const unsigned* b)
{
    asm volatile(
        "mma.sync.aligned.m16n8k16.row.col.f32.bf16.bf16.f32 "
        "{%0,%1,%2,%3}, {%4,%5,%6,%7}, {%8,%9}, {%0,%1,%2,%3};\n"
        : "+f"(c[0]), "+f"(c[1]), "+f"(c[2]), "+f"(c[3])
        : "r"(a[0]), "r"(a[1]), "r"(a[2]), "r"(a[3]), "r"(b[0]), "r"(b[1]));
}

__device__ __forceinline__ void ldsm4(unsigned* r, unsigned addr)
{
    asm volatile("ldmatrix.sync.aligned.m8n8.x4.shared.b16 {%0,%1,%2,%3}, [%4];\n"
                 : "=r"(r[0]), "=r"(r[1]), "=r"(r[2]), "=r"(r[3]) : "r"(addr));
}

__device__ __forceinline__ void ldsm4t(unsigned* r, unsigned addr)
{
    asm volatile("ldmatrix.sync.aligned.m8n8.x4.trans.shared.b16 {%0,%1,%2,%3}, [%4];\n"
                 : "=r"(r[0]), "=r"(r[1]), "=r"(r[2]), "=r"(r[3]) : "r"(addr));
}

__device__ __forceinline__ void cp16(unsigned dst, const void* src)
{
    asm volatile("cp.async.cg.shared.global [%0], [%1], 16;\n" :: "r"(dst), "l"(src));
}

__device__ __forceinline__ void load_W_async(
    unsigned dstHi, unsigned dstLo,
    const __nv_bfloat16* __restrict__ Whi, const __nv_bfloat16* __restrict__ Wlo,
    int row0, int kc, int tid)
{
    // 64 rows x 32 k bf16 = 4096 B each of hi/lo: one 16B seg per thread
    int row = tid >> 2, c16 = tid & 3;
    size_t go = (size_t)(row0 + row) * C_ + kc + c16 * 8;
    cp16(dstHi + row * 80 + c16 * 16, Whi + go);
    cp16(dstLo + row * 80 + c16 * 16, Wlo + go);
    asm volatile("cp.async.commit_group;\n" ::: "memory");
}

__device__ __forceinline__ void load_X(float4* xs, const float* __restrict__ xbase,
                                       int kc, int tid)
{
#pragma unroll
    for (int i = 0; i < 4; i++) {
        int u = i * 256 + tid;
        int k = u >> 5, c4 = (u & 31) << 2;
        xs[i] = *(const float4*)(xbase + (size_t)(kc + k) * HW_ + c4);
    }
}

__device__ __forceinline__ void store_X(const float4* xs, unsigned dstHi, unsigned dstLo,
                                        int tid)
{
#pragma unroll
    for (int i = 0; i < 4; i++) {
        int u = i * 256 + tid;
        int k = u >> 5, c4 = (u & 31) << 2;
        float4 v = xs[i];
        __nv_bfloat16 hx = __float2bfloat16(v.x), hy = __float2bfloat16(v.y);
        __nv_bfloat16 hz = __float2bfloat16(v.z), hw = __float2bfloat16(v.w);
        unsigned h0 = (unsigned)__bfloat16_as_ushort(hx) | ((unsigned)__bfloat16_as_ushort(hy) << 16);
        unsigned h1 = (unsigned)__bfloat16_as_ushort(hz) | ((unsigned)__bfloat16_as_ushort(hw) << 16);
        __nv_bfloat16 lx = __float2bfloat16(v.x - __bfloat162float(hx));
        __nv_bfloat16 ly = __float2bfloat16(v.y - __bfloat162float(hy));
        __nv_bfloat16 lz = __float2bfloat16(v.z - __bfloat162float(hz));
        __nv_bfloat16 lw = __float2bfloat16(v.w - __bfloat162float(hw));
        unsigned l0 = (unsigned)__bfloat16_as_ushort(lx) | ((unsigned)__bfloat16_as_ushort(ly) << 16);
        unsigned l1 = (unsigned)__bfloat16_as_ushort(lz) | ((unsigned)__bfloat16_as_ushort(lw) << 16);
        unsigned a = (unsigned)(k * XPITCH + c4) * 2;
        asm volatile("st.shared.v2.b32 [%0], {%1,%2};\n" :: "r"(dstHi + a), "r"(h0), "r"(h1) : "memory");
        asm volatile("st.shared.v2.b32 [%0], {%1,%2};\n" :: "r"(dstLo + a), "r"(l0), "r"(l1) : "memory");
    }
}

__device__ __forceinline__ void mma_stage(
    float acc[2][4][4], unsigned wHi, unsigned wLo, unsigned xHi, unsigned xLo,
    int wm, int wn, int lane)
{
    int lr = lane & 15, lc = lane >> 4;
#pragma unroll
    for (int ks = 0; ks < 2; ks++) {
        int k0 = ks * 16;
        unsigned Ah[2][4], Al[2][4], Bh[2][4], Bl[2][4];
#pragma unroll
        for (int mi = 0; mi < 2; mi++) {
            unsigned ra = (unsigned)((wm * 32 + mi * 16 + lr) * WPITCH + k0 + lc * 8) * 2;
            ldsm4(Ah[mi], wHi + ra);
            ldsm4(Al[mi], wLo + ra);
        }
#pragma unroll
        for (int p = 0; p < 2; p++) {
            unsigned rb = (unsigned)((k0 + lr) * XPITCH + wn * 32 + p * 16 + lc * 8) * 2;
            ldsm4t(Bh[p], xHi + rb);
            ldsm4t(Bl[p], xLo + rb);
        }
#pragma unroll
        for (int mi = 0; mi < 2; mi++)
#pragma unroll
            for (int ni = 0; ni < 4; ni++) {
                const unsigned* bh = &Bh[ni >> 1][(ni & 1) * 2];
                const unsigned* bl = &Bl[ni >> 1][(ni & 1) * 2];
                mma_bf16(acc[mi][ni], Ah[mi], bh);
                mma_bf16(acc[mi][ni], Ah[mi], bl);
                mma_bf16(acc[mi][ni], Al[mi], bh);
            }
    }
}

__global__ __launch_bounds__(256, 3) void gemm_kernel(
    const float* __restrict__ in, float* __restrict__ out,
    const __nv_bfloat16* __restrict__ Whi, const __nv_bfloat16* __restrict__ Wlo,
    const float* __restrict__ bias)
{
    extern __shared__ char dynsm[];
    unsigned sbase = (unsigned)__cvta_generic_to_shared(dynsm);

    int tid  = threadIdx.x;
    int warp = tid >> 5, lane = tid & 31;
    int g  = lane >> 2, t4 = lane & 3;
    int wm = warp >> 2, wn = warp & 3;          // warps: 2 (M) x 4 (N)
    int tile_m = blockIdx.x;                    // 0..3  (M=256 / 64)
    int tile_n = blockIdx.y;                    // 0..511 (N=65536 / 128)
    int b   = tile_n >> 5;
    int hw0 = (tile_n & 31) << 7;
    const float* xbase = in + (size_t)b * (C_ * HW_) + hw0;
    int row0 = tile_m * 64;

    float acc[2][4][4];
#pragma unroll
    for (int i = 0; i < 2; i++)
#pragma unroll
        for (int j = 0; j < 4; j++)
#pragma unroll
            for (int r = 0; r < 4; r++) acc[i][j][r] = 0.f;

    float4 xs[4];

    // prologue: fill stage 0
    load_X(xs, xbase, 0, tid);
    load_W_async(sbase + OFF_WHI, sbase + OFF_WLO, Whi, Wlo, row0, 0, tid);
    store_X(xs, sbase + OFF_XHI, sbase + OFF_XLO, tid);
    asm volatile("cp.async.wait_group 0;\n" ::: "memory");
    __syncthreads();

#pragma unroll 1
    for (int it = 0; it < 8; it++) {
        int cur = it & 1, nxt = cur ^ 1;
        if (it < 7) {
            load_X(xs, xbase, (it + 1) * 32, tid);
            load_W_async(sbase + OFF_WHI + nxt * SW_BYTES, sbase + OFF_WLO + nxt * SW_BYTES,
                         Whi, Wlo, row0, (it + 1) * 32, tid);
        }
        mma_stage(acc,
                  sbase + OFF_WHI + cur * SW_BYTES, sbase + OFF_WLO + cur * SW_BYTES,
                  sbase + OFF_XHI + cur * SX_BYTES, sbase + OFF_XLO + cur * SX_BYTES,
                  wm, wn, lane);
        if (it < 7) {
            store_X(xs, sbase + OFF_XHI + nxt * SX_BYTES, sbase + OFF_XLO + nxt * SX_BYTES, tid);
            asm volatile("cp.async.wait_group 0;\n" ::: "memory");
            __syncthreads();
        }
    }

    // epilogue: +bias, relu, write NCHW fp32
#pragma unroll
    for (int mi = 0; mi < 2; mi++) {
        int r0 = row0 + wm * 32 + mi * 16 + g;
        float bv0 = bias[r0], bv1 = bias[r0 + 8];
#pragma unroll
        for (int ni = 0; ni < 4; ni++) {
            int col = wn * 32 + ni * 8 + (t4 << 1);
            size_t o0 = ((size_t)b * C_ + r0) * HW_ + hw0 + col;
            float2 v0, v1;
            v0.x = fmaxf(acc[mi][ni][0] + bv0, 0.f);
            v0.y = fmaxf(acc[mi][ni][1] + bv0, 0.f);
            v1.x = fmaxf(acc[mi][ni][2] + bv1, 0.f);
            v1.y = fmaxf(acc[mi][ni][3] + bv1, 0.f);
            *(float2*)(out + o0)            = v0;
            *(float2*)(out + o0 + 8 * HW_)  = v1;
        }
    }
}

// ---------------- combined 9x9 depthwise (identity + 4 branches + biases) --
#define DPITCH 76
__global__ __launch_bounds__(256) void dw_kernel(
    const float* __restrict__ in, float* __restrict__ out)
{
    __shared__ float tile[72 * DPITCH];
    __shared__ float ws[81];
    __shared__ float sbias;

    int bc  = blockIdx.x;        // b*256 + c
    int c   = bc & 255;
    int tid = threadIdx.x;
    const float* src = in + (size_t)bc * HW_;

    if (tid < 81) ws[tid] = g_wd[c * 81 + tid];
    if (tid == 81) sbias = g_bd[c];

    for (int idx = tid; idx < 72 * 72; idx += 256) {
        int sr = idx / 72, sc = idx - sr * 72;
        int gr = sr - 4, gc = sc - 4;
        float v = 0.f;
        if ((unsigned)gr < 64u && (unsigned)gc < 64u) v = src[gr * 64 + gc];
        tile[sr * DPITCH + sc] = v;
    }
    __syncthreads();

    int orow = tid >> 2;
    int ocol = (tid & 3) << 4;      // 16 outputs per thread, one row strip
    float acc[16];
    float bv = sbias;
#pragma unroll
    for (int j = 0; j < 16; j++) acc[j] = bv;

#pragma unroll
    for (int r = 0; r < 9; r++) {
        float win[24];
        const float* rowp = &tile[(orow + r) * DPITCH + ocol];
#pragma unroll
        for (int q = 0; q < 6; q++) {
            float4 v = *(const float4*)(rowp + q * 4);
            win[q * 4]     = v.x; win[q * 4 + 1] = v.y;
            win[q * 4 + 2] = v.z; win[q * 4 + 3] = v.w;
        }
#pragma unroll
        for (int s = 0; s < 9; s++) {
            float w = ws[r * 9 + s];
#pragma unroll
            for (int j = 0; j < 16; j++) acc[j] = fmaf(win[j + s], w, acc[j]);
        }
    }

    float* dst = out + (size_t)bc * HW_ + orow * 64 + ocol;
#pragma unroll
    for (int q = 0; q < 4; q++) {
        float4 v;
        v.x = acc[q * 4]; v.y = acc[q * 4 + 1]; v.z = acc[q * 4 + 2]; v.w = acc[q * 4 + 3];
        *(float4*)(dst + q * 4) = v;
    }
}

// ---------------- launch ----------------------------------------------------
extern "C" void kernel_launch(void* const* d_in, const int* in_sizes, int n_in,
                              void* d_out, int out_size)
{
    const float* x     = (const float*)d_in[0];
    const float* pre_w = (const float*)d_in[1];
    const float* bn1g  = (const float*)d_in[2];
    const float* bn1b  = (const float*)d_in[3];
    const float* bn1m  = (const float*)d_in[4];
    const float* bn1v  = (const float*)d_in[5];
    const float* dw3w  = (const float*)d_in[6];
    const float* dw3b  = (const float*)d_in[7];
    const float* dw5w  = (const float*)d_in[8];
    const float* dw5b  = (const float*)d_in[9];
    const float* dw7w  = (const float*)d_in[10];
    const float* dw7b  = (const float*)d_in[11];
    const float* dw9w  = (const float*)d_in[12];
    const float* dw9b  = (const float*)d_in[13];
    const float* pw_w  = (const float*)d_in[14];
    const float* bn2g  = (const float*)d_in[15];
    const float* bn2b  = (const float*)d_in[16];
    const float* bn2m  = (const float*)d_in[17];
    const float* bn2v  = (const float*)d_in[18];
    const float* postw = (const float*)d_in[19];
    const float* bn3g  = (const float*)d_in[20];
    const float* bn3b  = (const float*)d_in[21];
    const float* bn3m  = (const float*)d_in[22];
    const float* bn3v  = (const float*)d_in[23];

    void *pA, *pB, *pw1h, *pw1l, *pw2h, *pw2l, *pw3h, *pw3l, *pb1, *pb2, *pb3;
    cudaGetSymbolAddress(&pA, g_bufA);
    cudaGetSymbolAddress(&pB, g_bufB);
    cudaGetSymbolAddress(&pw1h, g_w1_hi);
    cudaGetSymbolAddress(&pw1l, g_w1_lo);
    cudaGetSymbolAddress(&pw2h, g_w2_hi);
    cudaGetSymbolAddress(&pw2l, g_w2_lo);
    cudaGetSymbolAddress(&pw3h, g_w3_hi);
    cudaGetSymbolAddress(&pw3l, g_w3_lo);
    cudaGetSymbolAddress(&pb1, g_b1);
    cudaGetSymbolAddress(&pb2, g_b2);
    cudaGetSymbolAddress(&pb3, g_b3);

    cudaFuncSetAttribute(gemm_kernel, cudaFuncAttributeMaxDynamicSharedMemorySize, SMEM_TOT);

    fold_kernel<<<256, 256>>>(pre_w, bn1g, bn1b, bn1m, bn1v,
                              dw3w, dw3b, dw5w, dw5b, dw7w, dw7b, dw9w, dw9b,
                              pw_w, bn2g, bn2b, bn2m, bn2v,
                              postw, bn3g, bn3b, bn3m, bn3v);

    dim3 ggrid(4, 512);   // tile_m fastest: X-sharing CTAs are bid-adjacent
    // stage 1: h = relu(BN1(pre_conv(x)))       -> bufA
    gemm_kernel<<<ggrid, 256, SMEM_TOT>>>(x, (float*)pA,
                                (const __nv_bfloat16*)pw1h, (const __nv_bfloat16*)pw1l,
                                (const float*)pb1);
    // stage 2: s = combined 9x9 depthwise       -> bufB
    dw_kernel<<<B_ * C_, 256>>>((const float*)pA, (float*)pB);
    // stage 3: s2 = relu(BN2(pw_conv(s)))       -> bufA
    gemm_kernel<<<ggrid, 256, SMEM_TOT>>>((const float*)pB, (float*)pA,
                                (const __nv_bfloat16*)pw2h, (const __nv_bfloat16*)pw2l,
                                (const float*)pb2);
    // stage 4: out = relu(BN3(post_conv(s2)))   -> d_out
    gemm_kernel<<<ggrid, 256, SMEM_TOT>>>((const float*)pA, (float*)d_out,
                                (const __nv_bfloat16*)pw3h, (const __nv_bfloat16*)pw3l,
                                (const float*)pb3);
}

// round 12
// speedup vs baseline: 1.0405x; 1.0405x over previous
#include <cuda_runtime.h>
#include <cuda_bf16.h>
#include <cstdint>

#define B_   16
#define C_   256
#define HW_  4096          // 64*64
#define NTOT (B_ * C_ * HW_)

// ---------------- scratch + folded weights (device globals: no allocs) -----
__device__ float g_bufA[NTOT];                    // gemm1 out / dw in (fp32)
__device__ __nv_bfloat16 g_bh[NTOT], g_bl[NTOT];  // dw out    (hi/lo planes)
__device__ __nv_bfloat16 g_ah[NTOT], g_al[NTOT];  // gemm2 out (hi/lo planes)

__device__ __nv_bfloat16 g_w1_hi[C_ * C_], g_w1_lo[C_ * C_];
__device__ __nv_bfloat16 g_w2_hi[C_ * C_], g_w2_lo[C_ * C_];
__device__ __nv_bfloat16 g_w3_hi[C_ * C_], g_w3_lo[C_ * C_];
__device__ float g_b1[C_], g_b2[C_], g_b3[C_];
__device__ float g_wd[C_ * 81];   // combined 9x9 depthwise (incl. identity)
__device__ float g_bd[C_];        // combined depthwise bias

// ---------------- weight folding (BN -> 1x1 weights, 4 dw -> one 9x9) ------
__global__ void fold_kernel(
    const float* __restrict__ pre_w,
    const float* __restrict__ bn1_g, const float* __restrict__ bn1_b,
    const float* __restrict__ bn1_m, const float* __restrict__ bn1_v,
    const float* __restrict__ dw3_w, const float* __restrict__ dw3_b,
    const float* __restrict__ dw5_w, const float* __restrict__ dw5_b,
    const float* __restrict__ dw7_w, const float* __restrict__ dw7_b,
    const float* __restrict__ dw9_w, const float* __restrict__ dw9_b,
    const float* __restrict__ pw_w,
    const float* __restrict__ bn2_g, const float* __restrict__ bn2_b,
    const float* __restrict__ bn2_m, const float* __restrict__ bn2_v,
    const float* __restrict__ post_w,
    const float* __restrict__ bn3_g, const float* __restrict__ bn3_b,
    const float* __restrict__ bn3_m, const float* __restrict__ bn3_v)
{
    int oc = blockIdx.x;
    int ic = threadIdx.x;
    float s1 = bn1_g[oc] * rsqrtf(bn1_v[oc] + 1e-5f);
    float s2 = bn2_g[oc] * rsqrtf(bn2_v[oc] + 1e-5f);
    float s3 = bn3_g[oc] * rsqrtf(bn3_v[oc] + 1e-5f);
    int idx = oc * C_ + ic;

    float w1 = pre_w[idx] * s1;
    __nv_bfloat16 h1 = __float2bfloat16(w1);
    g_w1_hi[idx] = h1;
    g_w1_lo[idx] = __float2bfloat16(w1 - __bfloat162float(h1));

    float w2 = pw_w[idx] * s2;
    __nv_bfloat16 h2 = __float2bfloat16(w2);
    g_w2_hi[idx] = h2;
    g_w2_lo[idx] = __float2bfloat16(w2 - __bfloat162float(h2));

    float w3 = post_w[idx] * s3;
    __nv_bfloat16 h3 = __float2bfloat16(w3);
    g_w3_hi[idx] = h3;
    g_w3_lo[idx] = __float2bfloat16(w3 - __bfloat162float(h3));

    if (ic == 0) {
        g_b1[oc] = bn1_b[oc] - bn1_m[oc] * s1;
        g_b2[oc] = bn2_b[oc] - bn2_m[oc] * s2;
        g_b3[oc] = bn3_b[oc] - bn3_m[oc] * s3;
    }
    // combined depthwise 9x9 (cross-correlation, no flip; all same-padded)
    if (ic < 81) {
        int r = ic / 9, s = ic - 9 * r;
        float v = dw9_w[oc * 81 + ic];
        if (r >= 1 && r <= 7 && s >= 1 && s <= 7) v += dw7_w[oc * 49 + (r - 1) * 7 + (s - 1)];
        if (r >= 2 && r <= 6 && s >= 2 && s <= 6) v += dw5_w[oc * 25 + (r - 2) * 5 + (s - 2)];
        if (r >= 3 && r <= 5 && s >= 3 && s <= 5) v += dw3_w[oc * 9  + (r - 3) * 3 + (s - 3)];
        if (ic == 40) v += 1.0f;   // identity branch (center tap)
        g_wd[oc * 81 + ic] = v;
    }
    if (ic == 81) g_bd[oc] = dw3_b[oc] + dw5_b[oc] + dw7_b[oc] + dw9_b[oc];
}

// ---------------- bf16-split GEMM v6: 128x128 tile, hi/lo-plane streaming --
// C[oc][n] = relu( sum_ic W[oc][ic] * X[ic][n] + bias[oc] )
// Split: acc += Whi*Xhi + Whi*Xlo + Wlo*Xhi  (~fp32 accuracy)
// IN32 path (gemm1): X fp32 -> LDG + split + STS (v3 path).
// HILO path (gemm2/3): X already split into bf16 hi/lo planes by the
//   producer's epilogue -> cp.async straight into smem. No LDG-fp32,
//   no conversion, no STS. Bitwise-identical arithmetic to v3.

#define WPITCH 40
#define XPITCH 136
#define SW_BYTES (128 * WPITCH * 2)        // 10240 per stage (one of hi/lo)
#define SX_BYTES (32 * XPITCH * 2)         // 8704 per stage
#define OFF_WHI 0
#define OFF_WLO (2 * SW_BYTES)             // 20480
#define OFF_XHI (4 * SW_BYTES)             // 40960
#define OFF_XLO (OFF_XHI + 2 * SX_BYTES)   // 58368
#define SMEM_TOT (OFF_XLO + 2 * SX_BYTES)  // 75776

__device__ __forceinline__ void mma_bf16(float* c, const unsigned* a, const unsigned* b)
{
    asm volatile(
        "mma.sync.aligned.m16n8k16.row.col.f32.bf16.bf16.f32 "
        "{%0,%1,%2,%3}, {%4,%5,%6,%7}, {%8,%9}, {%0,%1,%2,%3};\n"
        : "+f"(c[0]), "+f"(c[1]), "+f"(c[2]), "+f"(c[3])
        : "r"(a[0]), "r"(a[1]), "r"(a[2]), "r"(a[3]), "r"(b[0]), "r"(b[1]));
}

__device__ __forceinline__ void ldsm4(unsigned* r, unsigned addr)
{
    asm volatile("ldmatrix.sync.aligned.m8n8.x4.shared.b16 {%0,%1,%2,%3}, [%4];\n"
                 : "=r"(r[0]), "=r"(r[1]), "=r"(r[2]), "=r"(r[3]) : "r"(addr));
}

__device__ __forceinline__ void ldsm4t(unsigned* r, unsigned addr)
{
    asm volatile("ldmatrix.sync.aligned.m8n8.x4.trans.shared.b16 {%0,%1,%2,%3}, [%4];\n"
                 : "=r"(r[0]), "=r"(r[1]), "=r"(r[2]), "=r"(r[3]) : "r"(addr));
}

__device__ __forceinline__ void cp16(unsigned dst, const void* src)
{
    asm volatile("cp.async.cg.shared.global [%0], [%1], 16;\n" :: "r"(dst), "l"(src));
}

__device__ __forceinline__ void load_W_async(
    unsigned dstHi, unsigned dstLo,
    const __nv_bfloat16* __restrict__ Whi, const __nv_bfloat16* __restrict__ Wlo,
    int row0, int kc, int tid)
{
#pragma unroll
    for (int t = 0; t < 2; t++) {
        int v = t * 256 + tid;
        int row = v >> 2, c16 = v & 3;
        size_t go = (size_t)(row0 + row) * C_ + kc + c16 * 8;
        cp16(dstHi + row * 80 + c16 * 16, Whi + go);
        cp16(dstLo + row * 80 + c16 * 16, Wlo + go);
    }
}

// HILO path: X tile 32(K) x 128(N) bf16, 16B segments from each plane
__device__ __forceinline__ void load_X_async(
    unsigned dstHi, unsigned dstLo,
    const __nv_bfloat16* __restrict__ xhiB, const __nv_bfloat16* __restrict__ xloB,
    int kc, int tid)
{
#pragma unroll
    for (int i = 0; i < 2; i++) {
        int s = i * 256 + tid;      // 0..511
        int k = s >> 4, sg = s & 15;
        size_t go = (size_t)(kc + k) * HW_ + sg * 8;
        unsigned a = (unsigned)(k * XPITCH + sg * 8) * 2;
        cp16(dstHi + a, xhiB + go);
        cp16(dstLo + a, xloB + go);
    }
}

__device__ __forceinline__ void load_X(float4* xs, const float* __restrict__ xbase,
                                       int kc, int tid)
{
#pragma unroll
    for (int i = 0; i < 4; i++) {
        int u = i * 256 + tid;
        int k = u >> 5, c4 = (u & 31) << 2;
        xs[i] = *(const float4*)(xbase + (size_t)(kc + k) * HW_ + c4);
    }
}

__device__ __forceinline__ void store_X(const float4* xs, unsigned dstHi, unsigned dstLo,
                                        int tid)
{
#pragma unroll
    for (int i = 0; i < 4; i++) {
        int u = i * 256 + tid;
        int k = u >> 5, c4 = (u & 31) << 2;
        float4 v = xs[i];
        __nv_bfloat16 hx = __float2bfloat16(v.x), hy = __float2bfloat16(v.y);
        __nv_bfloat16 hz = __float2bfloat16(v.z), hw = __float2bfloat16(v.w);
        unsigned h0 = (unsigned)__bfloat16_as_ushort(hx) | ((unsigned)__bfloat16_as_ushort(hy) << 16);
        unsigned h1 = (unsigned)__bfloat16_as_ushort(hz) | ((unsigned)__bfloat16_as_ushort(hw) << 16);
        __nv_bfloat16 lx = __float2bfloat16(v.x - __bfloat162float(hx));
        __nv_bfloat16 ly = __float2bfloat16(v.y - __bfloat162float(hy));
        __nv_bfloat16 lz = __float2bfloat16(v.z - __bfloat162float(hz));
        __nv_bfloat16 lw = __float2bfloat16(v.w - __bfloat162float(hw));
        unsigned l0 = (unsigned)__bfloat16_as_ushort(lx) | ((unsigned)__bfloat16_as_ushort(ly) << 16);
        unsigned l1 = (unsigned)__bfloat16_as_ushort(lz) | ((unsigned)__bfloat16_as_ushort(lw) << 16);
        unsigned a = (unsigned)(k * XPITCH + c4) * 2;
        asm volatile("st.shared.v2.b32 [%0], {%1,%2};\n" :: "r"(dstHi + a), "r"(h0), "r"(h1) : "memory");
        asm volatile("st.shared.v2.b32 [%0], {%1,%2};\n" :: "r"(dstLo + a), "r"(l0), "r"(l1) : "memory");
    }
}

__device__ __forceinline__ void mma_stage(
    float acc[4][4][4], unsigned wHi, unsigned wLo, unsigned xHi, unsigned xLo,
    int wm, int wn, int lane)
{
    int lr = lane & 15, lc = lane >> 4;
#pragma unroll
    for (int ks = 0; ks < 2; ks++) {
        int k0 = ks * 16;
        unsigned Ah[4][4], Al[4][4], Bh[2][4], Bl[2][4];
#pragma unroll
        for (int mi = 0; mi < 4; mi++) {
            unsigned ra = (unsigned)((wm * 64 + mi * 16 + lr) * WPITCH + k0 + lc * 8) * 2;
            ldsm4(Ah[mi], wHi + ra);
            ldsm4(Al[mi], wLo + ra);
        }
#pragma unroll
        for (int p = 0; p < 2; p++) {
            unsigned rb = (unsigned)((k0 + lr) * XPITCH + wn * 32 + p * 16 + lc * 8) * 2;
            ldsm4t(Bh[p], xHi + rb);
            ldsm4t(Bl[p], xLo + rb);
        }
#pragma unroll
        for (int mi = 0; mi < 4; mi++)
#pragma unroll
            for (int ni = 0; ni < 4; ni++) {
                const unsigned* bh = &Bh[ni >> 1][(ni & 1) * 2];
                const unsigned* bl = &Bl[ni >> 1][(ni & 1) * 2];
                mma_bf16(acc[mi][ni], Ah[mi], bh);
                mma_bf16(acc[mi][ni], Ah[mi], bl);
                mma_bf16(acc[mi][ni], Al[mi], bh);
            }
    }
}

__device__ __forceinline__ void split_pair_store(
    __nv_bfloat16* ph, __nv_bfloat16* pl, size_t off, float a, float b)
{
    __nv_bfloat16 ha = __float2bfloat16(a), hb = __float2bfloat16(b);
    unsigned hw = (unsigned)__bfloat16_as_ushort(ha) |
                  ((unsigned)__bfloat16_as_ushort(hb) << 16);
    __nv_bfloat16 la = __float2bfloat16(a - __bfloat162float(ha));
    __nv_bfloat16 lb = __float2bfloat16(b - __bfloat162float(hb));
    unsigned lw = (unsigned)__bfloat16_as_ushort(la) |
                  ((unsigned)__bfloat16_as_ushort(lb) << 16);
    *(unsigned*)(ph + off) = hw;
    *(unsigned*)(pl + off) = lw;
}

template<bool IN32, bool OUT32>
__global__ __launch_bounds__(256, 2) void gemm_kernel(
    const float* __restrict__ in32,
    const __nv_bfloat16* __restrict__ inHi, const __nv_bfloat16* __restrict__ inLo,
    float* __restrict__ out32,
    __nv_bfloat16* __restrict__ outHi, __nv_bfloat16* __restrict__ outLo,
    const __nv_bfloat16* __restrict__ Whi, const __nv_bfloat16* __restrict__ Wlo,
    const float* __restrict__ bias)
{
    extern __shared__ char dynsm[];
    unsigned sbase = (unsigned)__cvta_generic_to_shared(dynsm);

    int tid  = threadIdx.x;
    int warp = tid >> 5, lane = tid & 31;
    int g  = lane >> 2, t4 = lane & 3;
    int wm = warp >> 2, wn = warp & 3;          // warps: 2 (M) x 4 (N)
    int tile_m = blockIdx.x;                    // 0..1  (M=256 / 128)
    int tile_n = blockIdx.y;                    // 0..511 (N=65536 / 128)
    int b   = tile_n >> 5;
    int hw0 = (tile_n & 31) << 7;
    size_t nbase = (size_t)b * (C_ * HW_) + hw0;
    const float* xbase = in32 ? in32 + nbase : nullptr;
    const __nv_bfloat16* xhiB = inHi ? inHi + nbase : nullptr;
    const __nv_bfloat16* xloB = inLo ? inLo + nbase : nullptr;
    int row0 = tile_m * 128;

    float acc[4][4][4];
#pragma unroll
    for (int i = 0; i < 4; i++)
#pragma unroll
        for (int j = 0; j < 4; j++)
#pragma unroll
            for (int r = 0; r < 4; r++) acc[i][j][r] = 0.f;

    float4 xs[4];

    // prologue: fill stage 0
    if (IN32) load_X(xs, xbase, 0, tid);
    load_W_async(sbase + OFF_WHI, sbase + OFF_WLO, Whi, Wlo, row0, 0, tid);
    if (!IN32) load_X_async(sbase + OFF_XHI, sbase + OFF_XLO, xhiB, xloB, 0, tid);
    asm volatile("cp.async.commit_group;\n" ::: "memory");
    if (IN32) store_X(xs, sbase + OFF_XHI, sbase + OFF_XLO, tid);
    asm volatile("cp.async.wait_group 0;\n" ::: "memory");
    __syncthreads();

#pragma unroll 1
    for (int it = 0; it < 8; it++) {
        int cur = it & 1, nxt = cur ^ 1;
        if (it < 7) {
            if (IN32) load_X(xs, xbase, (it + 1) * 32, tid);
            load_W_async(sbase + OFF_WHI + nxt * SW_BYTES, sbase + OFF_WLO + nxt * SW_BYTES,
                         Whi, Wlo, row0, (it + 1) * 32, tid);
            if (!IN32) load_X_async(sbase + OFF_XHI + nxt * SX_BYTES,
                                    sbase + OFF_XLO + nxt * SX_BYTES,
                                    xhiB, xloB, (it + 1) * 32, tid);
            asm volatile("cp.async.commit_group;\n" ::: "memory");
        }
        mma_stage(acc,
                  sbase + OFF_WHI + cur * SW_BYTES, sbase + OFF_WLO + cur * SW_BYTES,
                  sbase + OFF_XHI + cur * SX_BYTES, sbase + OFF_XLO + cur * SX_BYTES,
                  wm, wn, lane);
        if (it < 7) {
            if (IN32) store_X(xs, sbase + OFF_XHI + nxt * SX_BYTES,
                              sbase + OFF_XLO + nxt * SX_BYTES, tid);
            asm volatile("cp.async.wait_group 0;\n" ::: "memory");
            __syncthreads();
        }
    }

    // epilogue: +bias, relu, write (fp32 or hi/lo planes)
#pragma unroll
    for (int mi = 0; mi < 4; mi++) {
        int r0 = row0 + wm * 64 + mi * 16 + g;
        float bv0 = bias[r0], bv1 = bias[r0 + 8];
#pragma unroll
        for (int ni = 0; ni < 4; ni++) {
            int col = wn * 32 + ni * 8 + (t4 << 1);
            size_t o0 = ((size_t)b * C_ + r0) * HW_ + hw0 + col;
            float a0 = fmaxf(acc[mi][ni][0] + bv0, 0.f);
            float a1 = fmaxf(acc[mi][ni][1] + bv0, 0.f);
            float a2 = fmaxf(acc[mi][ni][2] + bv1, 0.f);
            float a3 = fmaxf(acc[mi][ni][3] + bv1, 0.f);
            if (OUT32) {
                float2 v0; v0.x = a0; v0.y = a1;
                float2 v1; v1.x = a2; v1.y = a3;
                *(float2*)(out32 + o0)           = v0;
                *(float2*)(out32 + o0 + 8 * HW_) = v1;
            } else {
                split_pair_store(outHi, outLo, o0,            a0, a1);
                split_pair_store(outHi, outLo, o0 + 8 * HW_,  a2, a3);
            }
        }
    }
}

// ---------------- combined 9x9 depthwise: fp32 in, hi/lo-plane out ---------
#define DPITCH 76
__global__ __launch_bounds__(256) void dw_kernel(
    const float* __restrict__ in,
    __nv_bfloat16* __restrict__ outHi, __nv_bfloat16* __restrict__ outLo)
{
    __shared__ float tile[72 * DPITCH];
    __shared__ float ws[81];
    __shared__ float sbias;

    int bc  = blockIdx.x;        // b*256 + c
    int c   = bc & 255;
    int tid = threadIdx.x;
    const float* src = in + (size_t)bc * HW_;

    if (tid < 81) ws[tid] = g_wd[c * 81 + tid];
    if (tid == 81) sbias = g_bd[c];

    for (int idx = tid; idx < 72 * 72; idx += 256) {
        int sr = idx / 72, sc = idx - sr * 72;
        int gr = sr - 4, gc = sc - 4;
        float v = 0.f;
        if ((unsigned)gr < 64u && (unsigned)gc < 64u) v = src[gr * 64 + gc];
        tile[sr * DPITCH + sc] = v;
    }
    __syncthreads();

    int orow = tid >> 2;
    int ocol = (tid & 3) << 4;      // 16 outputs per thread, one row strip
    float acc[16];
    float bv = sbias;
#pragma unroll
    for (int j = 0; j < 16; j++) acc[j] = bv;

#pragma unroll
    for (int r = 0; r < 9; r++) {
        float win[24];
        const float* rowp = &tile[(orow + r) * DPITCH + ocol];
#pragma unroll
        for (int q = 0; q < 6; q++) {
            float4 v = *(const float4*)(rowp + q * 4);
            win[q * 4]     = v.x; win[q * 4 + 1] = v.y;
            win[q * 4 + 2] = v.z; win[q * 4 + 3] = v.w;
        }
#pragma unroll
        for (int s = 0; s < 9; s++) {
            float w = ws[r * 9 + s];
#pragma unroll
            for (int j = 0; j < 16; j++) acc[j] = fmaf(win[j + s], w, acc[j]);
        }
    }

    // split into hi/lo planes; 16 outputs -> 2x uint4 per plane
    unsigned hw[8], lw[8];
#pragma unroll
    for (int j = 0; j < 8; j++) {
        float a = acc[2 * j], b2 = acc[2 * j + 1];
        __nv_bfloat16 ha = __float2bfloat16(a), hb = __float2bfloat16(b2);
        hw[j] = (unsigned)__bfloat16_as_ushort(ha) |
                ((unsigned)__bfloat16_as_ushort(hb) << 16);
        __nv_bfloat16 la = __float2bfloat16(a - __bfloat162float(ha));
        __nv_bfloat16 lb = __float2bfloat16(b2 - __bfloat162float(hb));
        lw[j] = (unsigned)__bfloat16_as_ushort(la) |
                ((unsigned)__bfloat16_as_ushort(lb) << 16);
    }
    size_t base = (size_t)bc * HW_ + orow * 64 + ocol;
    uint4 h0 = make_uint4(hw[0], hw[1], hw[2], hw[3]);
    uint4 h1 = make_uint4(hw[4], hw[5], hw[6], hw[7]);
    uint4 l0 = make_uint4(lw[0], lw[1], lw[2], lw[3]);
    uint4 l1 = make_uint4(lw[4], lw[5], lw[6], lw[7]);
    *(uint4*)(outHi + base)     = h0;
    *(uint4*)(outHi + base + 8) = h1;
    *(uint4*)(outLo + base)     = l0;
    *(uint4*)(outLo + base + 8) = l1;
}

// ---------------- launch ----------------------------------------------------
extern "C" void kernel_launch(void* const* d_in, const int* in_sizes, int n_in,
                              void* d_out, int out_size)
{
    const float* x     = (const float*)d_in[0];
    const float* pre_w = (const float*)d_in[1];
    const float* bn1g  = (const float*)d_in[2];
    const float* bn1b  = (const float*)d_in[3];
    const float* bn1m  = (const float*)d_in[4];
    const float* bn1v  = (const float*)d_in[5];
    const float* dw3w  = (const float*)d_in[6];
    const float* dw3b  = (const float*)d_in[7];
    const float* dw5w  = (const float*)d_in[8];
    const float* dw5b  = (const float*)d_in[9];
    const float* dw7w  = (const float*)d_in[10];
    const float* dw7b  = (const float*)d_in[11];
    const float* dw9w  = (const float*)d_in[12];
    const float* dw9b  = (const float*)d_in[13];
    const float* pw_w  = (const float*)d_in[14];
    const float* bn2g  = (const float*)d_in[15];
    const float* bn2b  = (const float*)d_in[16];
    const float* bn2m  = (const float*)d_in[17];
    const float* bn2v  = (const float*)d_in[18];
    const float* postw = (const float*)d_in[19];
    const float* bn3g  = (const float*)d_in[20];
    const float* bn3b  = (const float*)d_in[21];
    const float* bn3m  = (const float*)d_in[22];
    const float* bn3v  = (const float*)d_in[23];

    void *pA, *pbh, *pbl, *pah, *pal;
    void *pw1h, *pw1l, *pw2h, *pw2l, *pw3h, *pw3l, *pb1, *pb2, *pb3;
    cudaGetSymbolAddress(&pA, g_bufA);
    cudaGetSymbolAddress(&pbh, g_bh);
    cudaGetSymbolAddress(&pbl, g_bl);
    cudaGetSymbolAddress(&pah, g_ah);
    cudaGetSymbolAddress(&pal, g_al);
    cudaGetSymbolAddress(&pw1h, g_w1_hi);
    cudaGetSymbolAddress(&pw1l, g_w1_lo);
    cudaGetSymbolAddress(&pw2h, g_w2_hi);
    cudaGetSymbolAddress(&pw2l, g_w2_lo);
    cudaGetSymbolAddress(&pw3h, g_w3_hi);
    cudaGetSymbolAddress(&pw3l, g_w3_lo);
    cudaGetSymbolAddress(&pb1, g_b1);
    cudaGetSymbolAddress(&pb2, g_b2);
    cudaGetSymbolAddress(&pb3, g_b3);

    cudaFuncSetAttribute(gemm_kernel<true,  true >, cudaFuncAttributeMaxDynamicSharedMemorySize, SMEM_TOT);
    cudaFuncSetAttribute(gemm_kernel<false, false>, cudaFuncAttributeMaxDynamicSharedMemorySize, SMEM_TOT);
    cudaFuncSetAttribute(gemm_kernel<false, true >, cudaFuncAttributeMaxDynamicSharedMemorySize, SMEM_TOT);

    fold_kernel<<<256, 256>>>(pre_w, bn1g, bn1b, bn1m, bn1v,
                              dw3w, dw3b, dw5w, dw5b, dw7w, dw7b, dw9w, dw9b,
                              pw_w, bn2g, bn2b, bn2m, bn2v,
                              postw, bn3g, bn3b, bn3m, bn3v);

    dim3 ggrid(2, 512);   // tile_m fastest: X-sharing CTAs are bid-adjacent
    // stage 1: h = relu(BN1(pre_conv(x)))            fp32 -> bufA (fp32)
    gemm_kernel<true, true><<<ggrid, 256, SMEM_TOT>>>(
        x, nullptr, nullptr,
        (float*)pA, nullptr, nullptr,
        (const __nv_bfloat16*)pw1h, (const __nv_bfloat16*)pw1l, (const float*)pb1);
    // stage 2: s = combined 9x9 depthwise            bufA -> hi/lo planes
    dw_kernel<<<B_ * C_, 256>>>((const float*)pA,
                                (__nv_bfloat16*)pbh, (__nv_bfloat16*)pbl);
    // stage 3: s2 = relu(BN2(pw_conv(s)))            hi/lo -> hi/lo planes
    gemm_kernel<false, false><<<ggrid, 256, SMEM_TOT>>>(
        nullptr, (const __nv_bfloat16*)pbh, (const __nv_bfloat16*)pbl,
        nullptr, (__nv_bfloat16*)pah, (__nv_bfloat16*)pal,
        (const __nv_bfloat16*)pw2h, (const __nv_bfloat16*)pw2l, (const float*)pb2);
    // stage 4: out = relu(BN3(post_conv(s2)))        hi/lo -> d_out (fp32)
    gemm_kernel<false, true><<<ggrid, 256, SMEM_TOT>>>(
        nullptr, (const __nv_bfloat16*)pah, (const __nv_bfloat16*)pal,
        (float*)d_out, nullptr, nullptr,
        (const __nv_bfloat16*)pw3h, (const __nv_bfloat16*)pw3l, (const float*)pb3);
}